// round 13
// baseline (speedup 1.0000x reference)
#include <cuda_runtime.h>

#define Tv 1000
#define Dv 1024
#define NWORK 592            // 4 blocks/SM x 148 SMs: all co-resident, wave 1

// Task queue layout: [16 wosum][per-batch: 125 xsum, 16 vsum, 4 row, 125 bcast]
#define PERB     270
#define T_TOTAL  (16 + 8 * PERB)   // 2176

// Scratch (__device__ globals per allocation rules)
__device__ float g_part[125 * 8 * 1024];   // per-chunk partial t-sums
__device__ float g_vsump[16 * 8 * 64];     // j-slice partials of vsum
__device__ float g_wosum[64 * 1024];       // sum_h Wo[h*64+d, n]
__device__ float g_row[8 * 1024];          // per-batch output row
__device__ unsigned int g_qhead;
__device__ unsigned int g_barW;
__device__ unsigned int g_barA[8], g_barB[8], g_barC[8];
__device__ unsigned int g_done;

static __device__ __forceinline__ void stcs128(float4* p, float4 v) {
    asm volatile("st.global.cs.v4.f32 [%0], {%1, %2, %3, %4};"
                 :: "l"(p), "f"(v.x), "f"(v.y), "f"(v.z), "f"(v.w) : "memory");
}
static __device__ __forceinline__ unsigned int vload(const unsigned int* p) {
    return *(const volatile unsigned int*)p;
}

__global__ void __launch_bounds__(256, 4)
mega_kernel(const float* __restrict__ x,  const float* __restrict__ Wv,
            const float* __restrict__ bv, const float* __restrict__ Wo,
            const float* __restrict__ bo, float* __restrict__ out)
{
    __shared__ int   s_task;
    __shared__ float s_xr[4][64];
    __shared__ float s_xs[64];
    __shared__ float s_p[4][64];
    __shared__ float s_vs[64];

    const int tid = threadIdx.x;

    for (;;) {
        if (tid == 0) s_task = (int)atomicAdd(&g_qhead, 1u);
        __syncthreads();
        const int t = s_task;
        __syncthreads();               // s_task consumed before next overwrite
        if (t >= T_TOTAL) break;

        if (t < 16) {
            // ---------------- WOSUM: fold Wo over heads (no deps) ----------
            const int w = t;           // 64-col slice
            const float4* Wo4 = (const float4*)Wo;
            float4*       Ws4 = (float4*)g_wosum;
            #pragma unroll
            for (int s = 0; s < 4; s++) {
                int slot = tid + s * 256;      // 0..1023
                int d    = slot >> 4;          // 0..63
                int f4   = slot & 15;          // 0..15 (16 float4 = 64 cols)
                float4 acc = make_float4(0.f, 0.f, 0.f, 0.f);
                #pragma unroll
                for (int h = 0; h < 16; h++) {
                    float4 v = Wo4[(size_t)(h * 64 + d) * 256 + w * 16 + f4];
                    acc.x += v.x; acc.y += v.y; acc.z += v.z; acc.w += v.w;
                }
                Ws4[(size_t)d * 256 + w * 16 + f4] = acc;
            }
            __threadfence();
            __syncthreads();
            if (tid == 0) atomicAdd(&g_barW, 1u);
        } else {
            const int r   = t - 16;
            const int b   = r / PERB;
            const int off = r % PERB;

            if (off < 125) {
                // ---------------- XSUM chunk (no deps) ----------------
                const int chunk = off;
                const int j4    = tid << 2;
                const float4* xp =
                    (const float4*)(x + ((size_t)b * Tv + chunk * 8) * Dv + j4);
                float4 v0 = xp[0*256], v1 = xp[1*256], v2 = xp[2*256], v3 = xp[3*256];
                float4 v4 = xp[4*256], v5 = xp[5*256], v6 = xp[6*256], v7 = xp[7*256];
                float4 acc;
                acc.x = ((v0.x+v1.x)+(v2.x+v3.x)) + ((v4.x+v5.x)+(v6.x+v7.x));
                acc.y = ((v0.y+v1.y)+(v2.y+v3.y)) + ((v4.y+v5.y)+(v6.y+v7.y));
                acc.z = ((v0.z+v1.z)+(v2.z+v3.z)) + ((v4.z+v5.z)+(v6.z+v7.z));
                acc.w = ((v0.w+v1.w)+(v2.w+v3.w)) + ((v4.w+v5.w)+(v6.w+v7.w));
                *(float4*)(g_part + ((size_t)(chunk * 8 + b)) * Dv + j4) = acc;
                __threadfence();
                __syncthreads();
                if (tid == 0) atomicAdd(&g_barA[b], 1u);
            } else if (off < 141) {
                // ---------------- VSUM j-slice: wait xsum[b] ----------------
                const int jb = off - 125;
                if (tid == 0) { while (vload(&g_barA[b]) < 125u) __nanosleep(64); }
                __syncthreads();

                const int j   = tid & 63;
                const int seg = tid >> 6;
                const int jg  = jb * 64;
                {
                    const int c0 = seg * 31;
                    const int cn = (seg == 3) ? 32 : 31;
                    float s = 0.f;
                    #pragma unroll 31
                    for (int c = 0; c < cn; c++)
                        s += g_part[((size_t)((c0 + c) * 8 + b)) * Dv + jg + j];
                    s_xr[seg][j] = s;
                }
                __syncthreads();
                if (seg == 0)
                    s_xs[j] = s_xr[0][j] + s_xr[1][j] + s_xr[2][j] + s_xr[3][j];
                __syncthreads();
                {
                    float acc = 0.f;
                    #pragma unroll
                    for (int jj = 0; jj < 16; jj++) {
                        int jl = seg * 16 + jj;
                        acc += s_xs[jl] * Wv[(size_t)(jg + jl) * 64 + j];
                    }
                    s_p[seg][j] = acc;
                }
                __syncthreads();
                if (seg == 0)
                    g_vsump[(jb * 8 + b) * 64 + j] =
                        s_p[0][j] + s_p[1][j] + s_p[2][j] + s_p[3][j];
                __threadfence();
                __syncthreads();
                if (tid == 0) atomicAdd(&g_barB[b], 1u);
            } else if (off < 145) {
                // ---------------- ROW quarter: wait vsum[b] + wosum ----------
                const int q = off - 141;
                if (tid == 0) {
                    while (vload(&g_barB[b]) < 16u || vload(&g_barW) < 16u)
                        __nanosleep(64);
                }
                __syncthreads();

                if (tid < 64) {
                    float s = (float)Tv * bv[tid];
                    #pragma unroll
                    for (int jb = 0; jb < 16; jb++)
                        s += g_vsump[(jb * 8 + b) * 64 + tid];
                    s_vs[tid] = s;
                }
                __syncthreads();

                const int n = q * 256 + tid;
                float acc = bo[n];
                #pragma unroll 8
                for (int d = 0; d < 64; d++)
                    acc = fmaf(s_vs[d], g_wosum[(size_t)d * Dv + n], acc);
                g_row[b * Dv + n] = acc;
                __threadfence();
                __syncthreads();
                if (tid == 0) atomicAdd(&g_barC[b], 1u);
            } else {
                // ---------------- BCAST chunk: wait row[b] ----------------
                const int chunk = off - 145;
                if (tid == 0) { while (vload(&g_barC[b]) < 4u) __nanosleep(64); }
                __syncthreads();

                float4 v = ((const float4*)g_row)[b * 256 + tid];
                float4* op = (float4*)out
                           + ((size_t)b * Tv + chunk * 8) * 256 + tid;
                stcs128(op + 0*256, v);  stcs128(op + 1*256, v);
                stcs128(op + 2*256, v);  stcs128(op + 3*256, v);
                stcs128(op + 4*256, v);  stcs128(op + 5*256, v);
                stcs128(op + 6*256, v);  stcs128(op + 7*256, v);
            }
        }
        __syncthreads();   // retire task before next grab overwrites s_task
    }

    // -------- Reset all counters for the next graph replay (last block) -----
    if (tid == 0) {
        unsigned int d = atomicAdd(&g_done, 1u);
        if (d == NWORK - 1u) {
            atomicExch(&g_qhead, 0u);
            atomicExch(&g_barW, 0u);
            #pragma unroll
            for (int i = 0; i < 8; i++) {
                atomicExch(&g_barA[i], 0u);
                atomicExch(&g_barB[i], 0u);
                atomicExch(&g_barC[i], 0u);
            }
            atomicExch(&g_done, 0u);
        }
    }
}

// ---------------------------------------------------------------------------
extern "C" void kernel_launch(void* const* d_in, const int* in_sizes, int n_in,
                              void* d_out, int out_size)
{
    const float* x  = (const float*)d_in[0];
    const float* Wv = (const float*)d_in[5];
    const float* bv = (const float*)d_in[6];
    const float* Wo = (const float*)d_in[7];
    const float* bo = (const float*)d_in[8];
    float* out = (float*)d_out;

    mega_kernel<<<NWORK, 256>>>(x, Wv, bv, Wo, bo, out);
}

// round 14
// speedup vs baseline: 1.2152x; 1.2152x over previous
#include <cuda_runtime.h>

#define Tv 1000
#define Dv 1024
#define NWORK 592            // 4 blocks/SM x 148 SMs: all co-resident, wave 1
#define T_TOTAL 2176

// Scratch (__device__ globals per allocation rules)
__device__ float g_part[125 * 8 * 1024];   // per-chunk partial t-sums
__device__ float g_vsump[16 * 8 * 64];     // j-slice partials of vsum
__device__ float g_wosum[64 * 1024];       // sum_h Wo[h*64+d, n]
__device__ float g_row[8 * 1024];          // per-batch output row
__device__ unsigned int g_qhead;
__device__ unsigned int g_barW;
__device__ unsigned int g_barA[8], g_barB[8], g_barC[8];
__device__ unsigned int g_done;

static __device__ __forceinline__ void stcs128(float4* p, float4 v) {
    asm volatile("st.global.cs.v4.f32 [%0], {%1, %2, %3, %4};"
                 :: "l"(p), "f"(v.x), "f"(v.y), "f"(v.z), "f"(v.w) : "memory");
}
static __device__ __forceinline__ unsigned int vload(const unsigned int* p) {
    return *(const volatile unsigned int*)p;
}

// Queue schedule (phase-bulked, read/write interleave in the middle):
//   [   0,  16) wosum w
//   [  16, 516) xsum  b0-3           (b=idx/125, chunk=idx%125)
//   [ 516, 580) vsum  b0-3           (b=idx/16,  jb=idx%16)
//   [ 580, 596) row   b0-3           (b=idx/4,   q=idx%4)
//   [ 596,1596) even: xsum b4-7 / odd: bcast b0-3
//   [1596,1660) vsum  b4-7
//   [1660,1676) row   b4-7
//   [1676,2176) bcast b4-7
// Kind: 0=wosum 1=xsum 2=vsum 3=row 4=bcast
static __device__ __forceinline__ void decode(int t, int& kind, int& b, int& p1)
{
    if (t < 16)        { kind = 0; b = 0; p1 = t; }
    else if (t < 516)  { int i = t - 16;   kind = 1; b = i / 125;     p1 = i % 125; }
    else if (t < 580)  { int i = t - 516;  kind = 2; b = i / 16;      p1 = i % 16; }
    else if (t < 596)  { int i = t - 580;  kind = 3; b = i / 4;       p1 = i % 4; }
    else if (t < 1596) {
        int i = t - 596;
        int j = i >> 1;
        if ((i & 1) == 0) { kind = 1; b = 4 + j / 125; p1 = j % 125; }
        else              { kind = 4; b = j / 125;     p1 = j % 125; }
    }
    else if (t < 1660) { int i = t - 1596; kind = 2; b = 4 + i / 16;  p1 = i % 16; }
    else if (t < 1676) { int i = t - 1660; kind = 3; b = 4 + i / 4;   p1 = i % 4; }
    else               { int i = t - 1676; kind = 4; b = 4 + i / 125; p1 = i % 125; }
}

__global__ void __launch_bounds__(256, 4)
mega_kernel(const float* __restrict__ x,  const float* __restrict__ Wv,
            const float* __restrict__ bv, const float* __restrict__ Wo,
            const float* __restrict__ bo, float* __restrict__ out)
{
    __shared__ int   s_task;
    __shared__ float s_xr[4][64];
    __shared__ float s_xs[64];
    __shared__ float s_p[4][64];
    __shared__ float s_vs[64];

    const int tid = threadIdx.x;

    for (;;) {
        if (tid == 0) s_task = (int)atomicAdd(&g_qhead, 1u);
        __syncthreads();
        const int t = s_task;
        __syncthreads();               // s_task consumed before next overwrite
        if (t >= T_TOTAL) break;

        int kind, b, p1;
        decode(t, kind, b, p1);

        if (kind == 0) {
            // ---------------- WOSUM: fold Wo over heads (no deps) ----------
            const int w = p1;
            const float4* Wo4 = (const float4*)Wo;
            float4*       Ws4 = (float4*)g_wosum;
            #pragma unroll
            for (int s = 0; s < 4; s++) {
                int slot = tid + s * 256;
                int d    = slot >> 4;
                int f4   = slot & 15;
                float4 acc = make_float4(0.f, 0.f, 0.f, 0.f);
                #pragma unroll
                for (int h = 0; h < 16; h++) {
                    float4 v = Wo4[(size_t)(h * 64 + d) * 256 + w * 16 + f4];
                    acc.x += v.x; acc.y += v.y; acc.z += v.z; acc.w += v.w;
                }
                Ws4[(size_t)d * 256 + w * 16 + f4] = acc;
            }
            __threadfence();
            __syncthreads();
            if (tid == 0) atomicAdd(&g_barW, 1u);
        } else if (kind == 1) {
            // ---------------- XSUM chunk (no deps) ----------------
            const int chunk = p1;
            const int j4    = tid << 2;
            const float4* xp =
                (const float4*)(x + ((size_t)b * Tv + chunk * 8) * Dv + j4);
            float4 v0 = xp[0*256], v1 = xp[1*256], v2 = xp[2*256], v3 = xp[3*256];
            float4 v4 = xp[4*256], v5 = xp[5*256], v6 = xp[6*256], v7 = xp[7*256];
            float4 acc;
            acc.x = ((v0.x+v1.x)+(v2.x+v3.x)) + ((v4.x+v5.x)+(v6.x+v7.x));
            acc.y = ((v0.y+v1.y)+(v2.y+v3.y)) + ((v4.y+v5.y)+(v6.y+v7.y));
            acc.z = ((v0.z+v1.z)+(v2.z+v3.z)) + ((v4.z+v5.z)+(v6.z+v7.z));
            acc.w = ((v0.w+v1.w)+(v2.w+v3.w)) + ((v4.w+v5.w)+(v6.w+v7.w));
            *(float4*)(g_part + ((size_t)(chunk * 8 + b)) * Dv + j4) = acc;
            __threadfence();
            __syncthreads();
            if (tid == 0) atomicAdd(&g_barA[b], 1u);
        } else if (kind == 2) {
            // ---------------- VSUM j-slice: wait xsum[b] ----------------
            const int jb = p1;
            if (tid == 0) { while (vload(&g_barA[b]) < 125u) __nanosleep(64); }
            __syncthreads();

            const int j   = tid & 63;
            const int seg = tid >> 6;
            const int jg  = jb * 64;
            {
                const int c0 = seg * 31;
                const int cn = (seg == 3) ? 32 : 31;
                float s = 0.f;
                #pragma unroll 31
                for (int c = 0; c < cn; c++)
                    s += g_part[((size_t)((c0 + c) * 8 + b)) * Dv + jg + j];
                s_xr[seg][j] = s;
            }
            __syncthreads();
            if (seg == 0)
                s_xs[j] = s_xr[0][j] + s_xr[1][j] + s_xr[2][j] + s_xr[3][j];
            __syncthreads();
            {
                float acc = 0.f;
                #pragma unroll
                for (int jj = 0; jj < 16; jj++) {
                    int jl = seg * 16 + jj;
                    acc += s_xs[jl] * Wv[(size_t)(jg + jl) * 64 + j];
                }
                s_p[seg][j] = acc;
            }
            __syncthreads();
            if (seg == 0)
                g_vsump[(jb * 8 + b) * 64 + j] =
                    s_p[0][j] + s_p[1][j] + s_p[2][j] + s_p[3][j];
            __threadfence();
            __syncthreads();
            if (tid == 0) atomicAdd(&g_barB[b], 1u);
        } else if (kind == 3) {
            // ---------------- ROW quarter: wait vsum[b] + wosum ----------
            const int q = p1;
            if (tid == 0) {
                while (vload(&g_barB[b]) < 16u || vload(&g_barW) < 16u)
                    __nanosleep(64);
            }
            __syncthreads();

            if (tid < 64) {
                float s = (float)Tv * bv[tid];
                #pragma unroll
                for (int jb = 0; jb < 16; jb++)
                    s += g_vsump[(jb * 8 + b) * 64 + tid];
                s_vs[tid] = s;
            }
            __syncthreads();

            const int n = q * 256 + tid;
            float acc = bo[n];
            #pragma unroll 8
            for (int d = 0; d < 64; d++)
                acc = fmaf(s_vs[d], g_wosum[(size_t)d * Dv + n], acc);
            g_row[b * Dv + n] = acc;
            __threadfence();
            __syncthreads();
            if (tid == 0) atomicAdd(&g_barC[b], 1u);
        } else {
            // ---------------- BCAST chunk: wait row[b] ----------------
            const int chunk = p1;
            if (tid == 0) { while (vload(&g_barC[b]) < 4u) __nanosleep(64); }
            __syncthreads();

            float4 v = ((const float4*)g_row)[b * 256 + tid];
            float4* op = (float4*)out + ((size_t)b * Tv + chunk * 8) * 256 + tid;
            stcs128(op + 0*256, v);  stcs128(op + 1*256, v);
            stcs128(op + 2*256, v);  stcs128(op + 3*256, v);
            stcs128(op + 4*256, v);  stcs128(op + 5*256, v);
            stcs128(op + 6*256, v);  stcs128(op + 7*256, v);
        }
        __syncthreads();   // retire task before next grab overwrites s_task
    }

    // -------- Reset all counters for the next graph replay (last block) -----
    if (tid == 0) {
        unsigned int d = atomicAdd(&g_done, 1u);
        if (d == NWORK - 1u) {
            atomicExch(&g_qhead, 0u);
            atomicExch(&g_barW, 0u);
            #pragma unroll
            for (int i = 0; i < 8; i++) {
                atomicExch(&g_barA[i], 0u);
                atomicExch(&g_barB[i], 0u);
                atomicExch(&g_barC[i], 0u);
            }
            atomicExch(&g_done, 0u);
        }
    }
}

// ---------------------------------------------------------------------------
extern "C" void kernel_launch(void* const* d_in, const int* in_sizes, int n_in,
                              void* d_out, int out_size)
{
    const float* x  = (const float*)d_in[0];
    const float* Wv = (const float*)d_in[5];
    const float* bv = (const float*)d_in[6];
    const float* Wo = (const float*)d_in[7];
    const float* bo = (const float*)d_in[8];
    float* out = (float*)d_out;

    mega_kernel<<<NWORK, 256>>>(x, Wv, bv, Wo, bo, out);
}

// round 15
// speedup vs baseline: 1.2955x; 1.0661x over previous
#include <cuda_runtime.h>

#define Tv 1000
#define Dv 1024
#define NCHUNK 125   // 125 chunks x 8 rows = 1000

// Scratch (__device__ globals per allocation rules)
__device__ float g_part[NCHUNK * 8 * 1024];  // per-chunk partial t-sums
__device__ float g_vsump[16 * 8 * 64];       // 16 j-slice partials of vsum
__device__ float g_row[8 * 1024];            // per-batch output row

// Streaming (evict-first) 128-bit store: keep `out` from polluting L2.
static __device__ __forceinline__ void stcs128(float4* p, float4 v) {
    asm volatile("st.global.cs.v4.f32 [%0], {%1, %2, %3, %4};"
                 :: "l"(p), "f"(v.x), "f"(v.y), "f"(v.z), "f"(v.w) : "memory");
}

// ---------------------------------------------------------------------------
// 1) Partial sums over t for 4 batches: grid (125, 4), 256 threads.
// ---------------------------------------------------------------------------
__global__ void __launch_bounds__(256)
xsum_part_kernel(const float* __restrict__ x, int b0)
{
    const int chunk = blockIdx.x;
    const int b     = blockIdx.y + b0;
    const int j4    = threadIdx.x << 2;

    const float4* xp = (const float4*)(x + ((size_t)b * Tv + chunk * 8) * Dv + j4);
    float4 v0 = xp[0 * 256], v1 = xp[1 * 256], v2 = xp[2 * 256], v3 = xp[3 * 256];
    float4 v4 = xp[4 * 256], v5 = xp[5 * 256], v6 = xp[6 * 256], v7 = xp[7 * 256];

    float4 acc;
    acc.x = ((v0.x + v1.x) + (v2.x + v3.x)) + ((v4.x + v5.x) + (v6.x + v7.x));
    acc.y = ((v0.y + v1.y) + (v2.y + v3.y)) + ((v4.y + v5.y) + (v6.y + v7.y));
    acc.z = ((v0.z + v1.z) + (v2.z + v3.z)) + ((v4.z + v5.z) + (v6.z + v7.z));
    acc.w = ((v0.w + v1.w) + (v2.w + v3.w)) + ((v4.w + v5.w) + (v6.w + v7.w));

    *(float4*)(g_part + ((size_t)(chunk * 8 + b)) * Dv + j4) = acc;
}

// ---------------------------------------------------------------------------
// 2) vsum partials for 4 batches: grid (4, 16), 256 threads.
// ---------------------------------------------------------------------------
__global__ void __launch_bounds__(256)
vsum_part_kernel(const float* __restrict__ Wv, int b0)
{
    __shared__ float xr[4][64];
    __shared__ float xs[64];
    __shared__ float p[4][64];
    const int b   = blockIdx.x + b0;
    const int jb  = blockIdx.y;
    const int tid = threadIdx.x;
    const int j   = tid & 63;
    const int seg = tid >> 6;
    const int jg  = jb * 64;

    {
        const int c0 = seg * 31;
        const int cn = (seg == 3) ? 32 : 31;
        float s = 0.f;
        #pragma unroll 31
        for (int c = 0; c < cn; c++)
            s += g_part[((size_t)((c0 + c) * 8 + b)) * Dv + jg + j];
        xr[seg][j] = s;
    }
    __syncthreads();
    if (seg == 0)
        xs[j] = xr[0][j] + xr[1][j] + xr[2][j] + xr[3][j];
    __syncthreads();

    {
        float acc = 0.f;
        #pragma unroll
        for (int jj = 0; jj < 16; jj++) {
            int jl = seg * 16 + jj;
            acc += xs[jl] * Wv[(size_t)(jg + jl) * 64 + j];
        }
        p[seg][j] = acc;
    }
    __syncthreads();
    if (seg == 0)
        g_vsump[(jb * 8 + b) * 64 + j] = p[0][j] + p[1][j] + p[2][j] + p[3][j];
}

// ---------------------------------------------------------------------------
// 3) row GEMV for 4 batches: grid 32 (32 cols each), 256 threads.
//    Warp w covers m in [w*128, w*128+128), folded (m, m+64) pairs.
// ---------------------------------------------------------------------------
__global__ void __launch_bounds__(256)
row_kernel(const float* __restrict__ Wo, const float* __restrict__ bv,
           const float* __restrict__ bo, int b0)
{
    __shared__ float vs[4 * 64];
    __shared__ float part[8][4][32];

    const int n0   = blockIdx.x * 32;
    const int tid  = threadIdx.x;
    const int lane = tid & 31;
    const int wid  = tid >> 5;
    const int n    = n0 + lane;

    // Assemble vsum for 4 batches: 256 values, one per thread.
    {
        const int d = tid & 63;
        const int b = tid >> 6;
        float s = (float)Tv * bv[d];
        #pragma unroll
        for (int jb = 0; jb < 16; jb++)
            s += g_vsump[(jb * 8 + b0 + b) * 64 + d];
        vs[tid] = s;
    }
    __syncthreads();

    float acc[4] = {};
    const int mbase = wid * 128;
    #pragma unroll 8
    for (int mm = 0; mm < 64; mm++) {
        float w1 = Wo[(size_t)(mbase + mm) * Dv + n];
        float w2 = Wo[(size_t)(mbase + mm + 64) * Dv + n];
        float w  = w1 + w2;
        #pragma unroll
        for (int b = 0; b < 4; b++)
            acc[b] = fmaf(vs[b * 64 + mm], w, acc[b]);
    }
    #pragma unroll
    for (int b = 0; b < 4; b++)
        part[wid][b][lane] = acc[b];
    __syncthreads();

    if (tid < 128) {
        int b = tid >> 5;
        float s = bo[n0 + (tid & 31)];
        #pragma unroll
        for (int w = 0; w < 8; w++)
            s += part[w][b][tid & 31];
        g_row[(b0 + b) * Dv + n0 + (tid & 31)] = s;
    }
}

// ---------------------------------------------------------------------------
// 4) Broadcast for 4 batches: grid (125, 4), 256 threads, 8 x STG.128.CS.
// ---------------------------------------------------------------------------
__global__ void __launch_bounds__(256)
bcast_kernel(float* __restrict__ out, int b0)
{
    const int chunk = blockIdx.x;
    const int b     = blockIdx.y + b0;

    float4 v = ((const float4*)g_row)[b * 256 + threadIdx.x];
    float4* op = (float4*)out + ((size_t)b * Tv + chunk * 8) * 256 + threadIdx.x;
    stcs128(op + 0 * 256, v);  stcs128(op + 1 * 256, v);
    stcs128(op + 2 * 256, v);  stcs128(op + 3 * 256, v);
    stcs128(op + 4 * 256, v);  stcs128(op + 5 * 256, v);
    stcs128(op + 6 * 256, v);  stcs128(op + 7 * 256, v);
}

// ---------------------------------------------------------------------------
extern "C" void kernel_launch(void* const* d_in, const int* in_sizes, int n_in,
                              void* d_out, int out_size)
{
    const float* x  = (const float*)d_in[0];
    const float* Wv = (const float*)d_in[5];
    const float* bv = (const float*)d_in[6];
    const float* Wo = (const float*)d_in[7];
    const float* bo = (const float*)d_in[8];
    float* out = (float*)d_out;

    // One-time host-side stream/event creation (no device memory; happens in
    // the eager correctness call, i.e. outside graph capture).
    static cudaStream_t s2 = nullptr;
    static cudaEvent_t  evA = nullptr, evB = nullptr;
    if (s2 == nullptr) {
        cudaStreamCreateWithFlags(&s2, cudaStreamNonBlocking);
        cudaEventCreateWithFlags(&evA, cudaEventDisableTiming);
        cudaEventCreateWithFlags(&evB, cudaEventDisableTiming);
    }

    // ---- Half A (batches 0-3) on the default stream ----
    xsum_part_kernel<<<dim3(NCHUNK, 4), 256>>>(x, 0);
    cudaEventRecord(evA, 0);                 // fork point after read A
    vsum_part_kernel<<<dim3(4, 16), 256>>>(Wv, 0);
    row_kernel<<<32, 256>>>(Wo, bv, bo, 0);
    bcast_kernel<<<dim3(NCHUNK, 4), 256>>>(out, 0);

    // ---- Half B (batches 4-7) on stream 2, staggered after read A ----
    cudaStreamWaitEvent(s2, evA, 0);
    xsum_part_kernel<<<dim3(NCHUNK, 4), 256, 0, s2>>>(x, 4);
    vsum_part_kernel<<<dim3(4, 16), 256, 0, s2>>>(Wv, 4);
    row_kernel<<<32, 256, 0, s2>>>(Wo, bv, bo, 4);
    bcast_kernel<<<dim3(NCHUNK, 4), 256, 0, s2>>>(out, 4);
    cudaEventRecord(evB, s2);

    // ---- Join back to the default stream ----
    cudaStreamWaitEvent(0, evB, 0);
}

// round 17
// speedup vs baseline: 1.4060x; 1.0853x over previous
#include <cuda_runtime.h>

#define Tv 1000
#define Dv 1024
#define NCHUNK 125   // 125 chunks x 8 rows = 1000

// Scratch (__device__ globals per allocation rules)
__device__ float g_part[NCHUNK * 8 * 1024];  // per-chunk partial t-sums
__device__ float g_vsump[16 * 8 * 64];       // 16 j-slice partials of vsum
__device__ float g_wosum[64 * 1024];         // sum_h Wo[h*64+d, n]
__device__ float g_row[8 * 1024];            // per-batch output row

// Streaming (evict-first) 128-bit store: keep `out` from polluting L2.
static __device__ __forceinline__ void stcs128(float4* p, float4 v) {
    asm volatile("st.global.cs.v4.f32 [%0], {%1, %2, %3, %4};"
                 :: "l"(p), "f"(v.x), "f"(v.y), "f"(v.z), "f"(v.w) : "memory");
}

// ---------------------------------------------------------------------------
// 0) WoSum[d,n] = sum_h Wo[h*64+d, n]. grid 64, 256 threads, float4.
//    Dependency-free: runs on stream 2 concurrent with xsum.
// ---------------------------------------------------------------------------
__global__ void __launch_bounds__(256)
wosum_kernel(const float* __restrict__ Wo)
{
    const int f4 = blockIdx.x * 256 + threadIdx.x;  // 0..16383
    const int d  = f4 >> 8;                         // 0..63
    const int n4 = (f4 & 255) << 2;                 // 0..1020

    float4 acc = make_float4(0.f, 0.f, 0.f, 0.f);
    #pragma unroll
    for (int h = 0; h < 16; h++) {
        float4 v = *(const float4*)(Wo + ((size_t)(h * 64 + d)) * Dv + n4);
        acc.x += v.x; acc.y += v.y; acc.z += v.z; acc.w += v.w;
    }
    *(float4*)(g_wosum + (size_t)d * Dv + n4) = acc;
}

// ---------------------------------------------------------------------------
// 1) Partial sums over t: grid (125, 8), 256 threads, 8 batched LDG.128.
// ---------------------------------------------------------------------------
__global__ void __launch_bounds__(256)
xsum_part_kernel(const float* __restrict__ x)
{
    const int chunk = blockIdx.x;
    const int b     = blockIdx.y;
    const int j4    = threadIdx.x << 2;

    const float4* xp = (const float4*)(x + ((size_t)b * Tv + chunk * 8) * Dv + j4);
    float4 v0 = xp[0 * 256], v1 = xp[1 * 256], v2 = xp[2 * 256], v3 = xp[3 * 256];
    float4 v4 = xp[4 * 256], v5 = xp[5 * 256], v6 = xp[6 * 256], v7 = xp[7 * 256];

    float4 acc;
    acc.x = ((v0.x + v1.x) + (v2.x + v3.x)) + ((v4.x + v5.x) + (v6.x + v7.x));
    acc.y = ((v0.y + v1.y) + (v2.y + v3.y)) + ((v4.y + v5.y) + (v6.y + v7.y));
    acc.z = ((v0.z + v1.z) + (v2.z + v3.z)) + ((v4.z + v5.z) + (v6.z + v7.z));
    acc.w = ((v0.w + v1.w) + (v2.w + v3.w)) + ((v4.w + v5.w) + (v6.w + v7.w));

    *(float4*)(g_part + ((size_t)(chunk * 8 + b)) * Dv + j4) = acc;
}

// ---------------------------------------------------------------------------
// 2) vsum partials: grid (8 b, 16 jb). Each block owns a 64-wide j slice.
// ---------------------------------------------------------------------------
__global__ void __launch_bounds__(256)
vsum_part_kernel(const float* __restrict__ Wv)
{
    __shared__ float xr[4][64];
    __shared__ float xs[64];
    __shared__ float p[4][64];
    const int b   = blockIdx.x;
    const int jb  = blockIdx.y;
    const int tid = threadIdx.x;
    const int j   = tid & 63;
    const int seg = tid >> 6;
    const int jg  = jb * 64;

    {
        const int c0 = seg * 31;
        const int cn = (seg == 3) ? 32 : 31;
        float s = 0.f;
        #pragma unroll 31
        for (int c = 0; c < cn; c++)
            s += g_part[((size_t)((c0 + c) * 8 + b)) * Dv + jg + j];
        xr[seg][j] = s;
    }
    __syncthreads();
    if (seg == 0)
        xs[j] = xr[0][j] + xr[1][j] + xr[2][j] + xr[3][j];
    __syncthreads();

    {
        float acc = 0.f;
        #pragma unroll
        for (int jj = 0; jj < 16; jj++) {
            int jl = seg * 16 + jj;
            acc += xs[jl] * Wv[(size_t)(jg + jl) * 64 + j];
        }
        p[seg][j] = acc;
    }
    __syncthreads();
    if (seg == 0)
        g_vsump[(jb * 8 + b) * 64 + j] = p[0][j] + p[1][j] + p[2][j] + p[3][j];
}

// ---------------------------------------------------------------------------
// 3) row[b,n] = bo[n] + sum_d vs[b,d] * WoSum[d,n]. grid 32, 256 threads.
//    Reads pre-folded g_wosum (256 KB total, L2-hot) instead of Wo (4 MB).
//    Warp w covers d in [w*8, w*8+8).
// ---------------------------------------------------------------------------
__global__ void __launch_bounds__(256)
row_kernel(const float* __restrict__ bv, const float* __restrict__ bo)
{
    __shared__ float vs[8 * 64];
    __shared__ float part[8][8][32];

    const int n0   = blockIdx.x * 32;
    const int tid  = threadIdx.x;
    const int lane = tid & 31;
    const int wid  = tid >> 5;
    const int n    = n0 + lane;

    // Assemble vsum: 16 j-slice partials + T*bv. 512 outputs, 2 per thread.
    #pragma unroll
    for (int i = tid; i < 512; i += 256) {
        int d = i & 63;
        float s = (float)Tv * bv[d];
        #pragma unroll
        for (int jb = 0; jb < 16; jb++)
            s += g_vsump[jb * 512 + i];
        vs[i] = s;
    }
    __syncthreads();

    float acc[8] = {};
    const int dbase = wid * 8;
    #pragma unroll
    for (int dd = 0; dd < 8; dd++) {
        float w = g_wosum[(size_t)(dbase + dd) * Dv + n];
        #pragma unroll
        for (int b = 0; b < 8; b++)
            acc[b] = fmaf(vs[b * 64 + dbase + dd], w, acc[b]);
    }
    #pragma unroll
    for (int b = 0; b < 8; b++)
        part[wid][b][lane] = acc[b];
    __syncthreads();

    {
        int b = wid;
        float s = bo[n];
        #pragma unroll
        for (int w = 0; w < 8; w++)
            s += part[w][b][lane];
        g_row[b * Dv + n] = s;
    }
}

// ---------------------------------------------------------------------------
// 4) Broadcast: grid (125, 8), 256 threads. One float4/thread from g_row,
//    8 streaming STG.128.CS rows (evict-first: don't pollute L2).
// ---------------------------------------------------------------------------
__global__ void __launch_bounds__(256)
bcast_kernel(float* __restrict__ out)
{
    const int chunk = blockIdx.x;
    const int b     = blockIdx.y;

    float4 v = ((const float4*)g_row)[b * 256 + threadIdx.x];
    float4* op = (float4*)out + ((size_t)b * Tv + chunk * 8) * 256 + threadIdx.x;
    stcs128(op + 0 * 256, v);  stcs128(op + 1 * 256, v);
    stcs128(op + 2 * 256, v);  stcs128(op + 3 * 256, v);
    stcs128(op + 4 * 256, v);  stcs128(op + 5 * 256, v);
    stcs128(op + 6 * 256, v);  stcs128(op + 7 * 256, v);
}

// ---------------------------------------------------------------------------
extern "C" void kernel_launch(void* const* d_in, const int* in_sizes, int n_in,
                              void* d_out, int out_size)
{
    const float* x  = (const float*)d_in[0];
    const float* Wv = (const float*)d_in[5];
    const float* bv = (const float*)d_in[6];
    const float* Wo = (const float*)d_in[7];
    const float* bo = (const float*)d_in[8];
    float* out = (float*)d_out;

    // One-time host-side stream/event creation (no device memory; created in
    // the eager correctness call, outside graph capture).
    static cudaStream_t s2 = nullptr;
    static cudaEvent_t  evFork = nullptr, evW = nullptr;
    if (s2 == nullptr) {
        cudaStreamCreateWithFlags(&s2, cudaStreamNonBlocking);
        cudaEventCreateWithFlags(&evFork, cudaEventDisableTiming);
        cudaEventCreateWithFlags(&evW,    cudaEventDisableTiming);
    }

    // Legal capture fork: s2 must first wait on an event recorded on the
    // origin stream (stream 0) so it joins the captured graph.
    cudaEventRecord(evFork, 0);
    cudaStreamWaitEvent(s2, evFork, 0);

    // Wo head-fold on stream 2, concurrent with xsum (no data deps).
    wosum_kernel<<<64, 256, 0, s2>>>(Wo);
    cudaEventRecord(evW, s2);

    xsum_part_kernel<<<dim3(NCHUNK, 8), 256>>>(x);
    vsum_part_kernel<<<dim3(8, 16), 256>>>(Wv);
    cudaStreamWaitEvent(0, evW, 0);      // row needs g_wosum
    row_kernel<<<32, 256>>>(bv, bo);
    bcast_kernel<<<dim3(NCHUNK, 8), 256>>>(out);
}